// round 14
// baseline (speedup 1.0000x reference)
#include <cuda_runtime.h>
#include <cuda_fp16.h>
#include <cstdint>
#include <math_constants.h>

#define B_ 32
#define S_ 2048
#define H_ 1024

// Scratch (no device allocation allowed)
__device__ float  g_qadd[B_ * H_];          // Wa_b + Ua_b + query @ Wa^T   [B,H]
__device__ float  g_scores[B_ * S_];        // pre-softmax scores           [B,S]
__device__ float  g_ctxp[16 * B_ * H_];     // K4 split-S partials
__device__ __half g_keys_h[B_ * S_ * H_];   // fp16 copy of keys (134 MB)
__device__ __half g_Ua_h[H_ * H_];          // fp16 copy of Ua   (2 MB)

__device__ __forceinline__ float tanh_fast(float x) {
    float y;
    asm("tanh.approx.f32 %0, %1;" : "=f"(y) : "f"(x));
    return y;
}

__device__ __forceinline__ uint32_t smem_u32(const void* p) {
    uint32_t a;
    asm("{ .reg .u64 t; cvta.to.shared.u64 t, %1; cvt.u32.u64 %0, t; }" : "=r"(a) : "l"(p));
    return a;
}

__device__ __forceinline__ void ldsm4(uint32_t& r0, uint32_t& r1, uint32_t& r2, uint32_t& r3,
                                      uint32_t addr) {
    asm volatile("ldmatrix.sync.aligned.m8n8.x4.shared.b16 {%0,%1,%2,%3}, [%4];"
                 : "=r"(r0), "=r"(r1), "=r"(r2), "=r"(r3) : "r"(addr));
}

// ---------------------------------------------------------------------------
// K0: fp32 -> fp16 conversion, keys + Ua in one launch (8 elems/thread).
// ---------------------------------------------------------------------------
#define KEYS_BLKS ((B_ * S_ * H_) / 2048)   // 32768
#define UA_BLKS   ((H_ * H_) / 2048)        // 512

__global__ void k0_cvt2(const float* __restrict__ keys, __half* __restrict__ keys_h,
                        const float* __restrict__ Ua,   __half* __restrict__ Ua_h) {
    int bx = blockIdx.x;
    const float* src;
    __half* dst;
    int base;
    if (bx < KEYS_BLKS) { src = keys; dst = keys_h; base = bx; }
    else                { src = Ua;   dst = Ua_h;   base = bx - KEYS_BLKS; }
    int i = (base * 256 + threadIdx.x) * 8;
    float4 f0 = *(const float4*)(src + i);
    float4 f1 = *(const float4*)(src + i + 4);
    __half2 h[4];
    h[0] = __floats2half2_rn(f0.x, f0.y);
    h[1] = __floats2half2_rn(f0.z, f0.w);
    h[2] = __floats2half2_rn(f1.x, f1.y);
    h[3] = __floats2half2_rn(f1.z, f1.w);
    *(uint4*)(dst + i) = *(uint4*)h;
}

// ---------------------------------------------------------------------------
// K1: qadd[b][g] = Wa_b[g] + Ua_b[g] + sum_h query[b][h] * Wa_w[g][h]
// ---------------------------------------------------------------------------
__global__ void k1_qproj(const float* __restrict__ query,
                         const float* __restrict__ Wa_w,
                         const float* __restrict__ Wa_b,
                         const float* __restrict__ Ua_b) {
    int b = blockIdx.x;
    int g0 = blockIdx.y * 128;
    __shared__ float q_s[H_];
    for (int i = threadIdx.x; i < H_; i += blockDim.x)
        q_s[i] = query[b * H_ + i];
    __syncthreads();

    int warp = threadIdx.x >> 5;
    int lane = threadIdx.x & 31;
    for (int gi = 0; gi < 16; gi++) {
        int g = g0 + warp * 16 + gi;
        const float* wrow = Wa_w + (size_t)g * H_;
        float acc = 0.f;
        #pragma unroll 8
        for (int h = lane; h < H_; h += 32)
            acc += q_s[h] * wrow[h];
        #pragma unroll
        for (int off = 16; off; off >>= 1)
            acc += __shfl_xor_sync(0xffffffffu, acc, off);
        if (lane == 0)
            g_qadd[b * H_ + g] = acc + Wa_b[g] + Ua_b[g];
    }
}

// ---------------------------------------------------------------------------
// K2: fused scores GEMM, mma.sync.m16n8k16.f16 + ldmatrix, with FRAGMENT
// DOUBLE-BUFFERING: k16+1's LDSM issue before k16's HMMA (volatile order
// preserved, no dependence) so LDSM latency hides under the tensor pipe.
// __launch_bounds__(128, 3): ~170-reg budget fits the duplicate frag sets
// without spills; 3 CTAs/SM (work-stealing scheduler, no wave cliff).
// CTA tile M=64 x N=128, 4 warps (warp tile 32x64), TK=64, 2-stage cp.async.
// Row pitch 72 halves (144 B): LDSM phase addresses conflict-free.
// ---------------------------------------------------------------------------
#define TM 64
#define TN 128
#define TK 64                          // halves per k-chunk
#define NCHUNK (H_ / TK)               // 16 per nt
#define NT (H_ / TN)                   // 8 feature tiles
#define TOTC (NT * NCHUNK)             // 128 global chunks
#define SPADH 72                       // halves per row (144 B pitch)
#define A_TILE_B (TM * SPADH * 2)      // 9216 bytes
#define B_TILE_B (TN * SPADH * 2)      // 18432 bytes
// dynamic smem byte offsets
#define SM_SC  0                       // 64 floats
#define SM_QV  256                     // 128 floats
#define SM_VA  768                     // 128 floats
#define SM_A   1536                    // 2 buffers x 9216
#define SM_B   (SM_A + 2 * A_TILE_B)   // 2 buffers x 18432
#define SM_TOTAL (SM_B + 2 * B_TILE_B) // 56832

__device__ __forceinline__ void cp16(uint32_t dst, const void* src) {
    asm volatile("cp.async.cg.shared.global [%0], [%1], 16;" :: "r"(dst), "l"(src));
}

// 128 threads stage A tile (64 rows x 8 x 16B): 4 cp.async/thread.
__device__ __forceinline__ void stage_A(const __half* __restrict__ src,
                                        int kt, uint32_t buf) {
    int tid = threadIdx.x;
    #pragma unroll
    for (int i = 0; i < 4; i++) {
        int idx = i * 128 + tid;
        int row = idx >> 3, c = idx & 7;
        cp16(buf + (uint32_t)(row * (SPADH * 2) + c * 16),
             src + (size_t)row * H_ + kt * TK + c * 8);
    }
}

// 128 threads stage B tile (128 rows x 8 x 16B): 8 cp.async/thread.
__device__ __forceinline__ void stage_B(const __half* __restrict__ src,
                                        int kt, uint32_t buf) {
    int tid = threadIdx.x;
    #pragma unroll
    for (int i = 0; i < 8; i++) {
        int idx = i * 128 + tid;
        int row = idx >> 3, c = idx & 7;
        cp16(buf + (uint32_t)(row * (SPADH * 2) + c * 16),
             src + (size_t)row * H_ + kt * TK + c * 8);
    }
}

// Stage global chunk kc: keys k-chunk (kc & 15), Ua feature-block (kc >> 4).
__device__ __forceinline__ void stage_chunk(const __half* __restrict__ keys_blk,
                                            int kc, uint32_t sb) {
    int nb  = kc & 1;
    int knt = kc >> 4;
    int kkt = kc & 15;
    stage_A(keys_blk, kkt, sb + SM_A + nb * A_TILE_B);
    stage_B(g_Ua_h + (size_t)(knt * TN) * H_, kkt, sb + SM_B + nb * B_TILE_B);
    asm volatile("cp.async.commit_group;" ::: "memory");
}

__global__ __launch_bounds__(128, 3) void k2_scores(
    const float* __restrict__ Va_w,
    const float* __restrict__ Va_b) {

    extern __shared__ char smem[];
    uint32_t sb = smem_u32(smem);
    float* sc_s = (float*)(smem + SM_SC);
    float* qv_s = (float*)(smem + SM_QV);
    float* va_s = (float*)(smem + SM_VA);

    int tid  = threadIdx.x;
    int wid  = tid >> 5;
    int lane = tid & 31;
    int wm   = wid >> 1;          // 0..1 (32-row strips)
    int wn   = wid & 1;           // 0..1 (64-col strips)
    int grp  = lane >> 2;         // 0..7
    int qid  = lane & 3;          // 0..3

    // ldmatrix per-lane address components (halves)
    int a_row  = (lane & 7) + ((lane >> 3) & 1) * 8;
    int a_koff = ((lane >> 4) & 1) * 8;
    int b_n    = (lane & 7) + ((lane >> 4) & 1) * 8;
    int b_koff = ((lane >> 3) & 1) * 8;

    int blk = blockIdx.x;
    int b   = blk >> 5;                 // 32 s-tiles per batch
    int s0  = (blk & 31) * TM;
    const __half* keys_blk = g_keys_h + ((size_t)b * S_ + s0) * H_;

    if (tid < TM) sc_s[tid] = 0.f;

    float part[4] = {0.f, 0.f, 0.f, 0.f};

    for (int nt = 0; nt < NT; nt++) {
        __syncthreads();   // prev epilogue reads done before qv_s/va_s rewrite
        qv_s[tid] = g_qadd[b * H_ + nt * TN + tid];
        va_s[tid] = Va_w[nt * TN + tid];

        if (nt == 0)
            stage_chunk(keys_blk, 0, sb);   // prologue: stage global chunk 0

        float acc[2][8][4];
        #pragma unroll
        for (int mi = 0; mi < 2; mi++)
            #pragma unroll
            for (int ni = 0; ni < 8; ni++)
                #pragma unroll
                for (int c = 0; c < 4; c++)
                    acc[mi][ni][c] = 0.f;

        for (int kt = 0; kt < NCHUNK; kt++) {
            int kc  = nt * NCHUNK + kt;
            int cur = kc & 1;

            asm volatile("cp.async.wait_group 0;" ::: "memory");
            __syncthreads();   // chunk kc visible; reads of buf cur^1 done

            if (kc + 1 < TOTC)
                stage_chunk(keys_blk, kc + 1, sb);   // overlaps compute of kc

            uint32_t aba = sb + SM_A + cur * A_TILE_B;
            uint32_t bba = sb + SM_B + cur * B_TILE_B;
            uint32_t aaddr[2], baddr[4];
            #pragma unroll
            for (int mi = 0; mi < 2; mi++)
                aaddr[mi] = aba + (uint32_t)(((wm * 32 + mi * 16 + a_row) * SPADH + a_koff) * 2);
            #pragma unroll
            for (int p = 0; p < 4; p++)
                baddr[p] = bba + (uint32_t)(((wn * 64 + p * 16 + b_n) * SPADH + b_koff) * 2);

            // Double-buffered fragment sets: load set (k16+1)&1 before
            // HMMA on set k16&1 — LDSM latency hidden under tensor work.
            uint32_t af[2][2][4];
            uint32_t bf[2][8][2];

            // prologue: set 0 <- k16=0
            #pragma unroll
            for (int mi = 0; mi < 2; mi++)
                ldsm4(af[0][mi][0], af[0][mi][1], af[0][mi][2], af[0][mi][3], aaddr[mi]);
            #pragma unroll
            for (int p = 0; p < 4; p++)
                ldsm4(bf[0][2*p][0], bf[0][2*p][1], bf[0][2*p+1][0], bf[0][2*p+1][1], baddr[p]);

            #pragma unroll
            for (int k16 = 0; k16 < TK / 16; k16++) {
                int cs = k16 & 1;
                int ns = cs ^ 1;
                if (k16 + 1 < TK / 16) {
                    uint32_t kb = (k16 + 1) * 32;   // bytes: 16 halves
                    #pragma unroll
                    for (int mi = 0; mi < 2; mi++)
                        ldsm4(af[ns][mi][0], af[ns][mi][1], af[ns][mi][2], af[ns][mi][3],
                              aaddr[mi] + kb);
                    #pragma unroll
                    for (int p = 0; p < 4; p++)
                        ldsm4(bf[ns][2*p][0], bf[ns][2*p][1], bf[ns][2*p+1][0], bf[ns][2*p+1][1],
                              baddr[p] + kb);
                }
                #pragma unroll
                for (int mi = 0; mi < 2; mi++)
                    #pragma unroll
                    for (int ni = 0; ni < 8; ni++) {
                        asm volatile(
                            "mma.sync.aligned.m16n8k16.row.col.f32.f16.f16.f32 "
                            "{%0,%1,%2,%3}, {%4,%5,%6,%7}, {%8,%9}, {%0,%1,%2,%3};\n"
                            : "+f"(acc[mi][ni][0]), "+f"(acc[mi][ni][1]),
                              "+f"(acc[mi][ni][2]), "+f"(acc[mi][ni][3])
                            : "r"(af[cs][mi][0]), "r"(af[cs][mi][1]),
                              "r"(af[cs][mi][2]), "r"(af[cs][mi][3]),
                              "r"(bf[cs][ni][0]), "r"(bf[cs][ni][1]));
                    }
            }
        }

        // Epilogue: tanh + Va fold into per-row partials.
        #pragma unroll
        for (int ni = 0; ni < 8; ni++) {
            #pragma unroll
            for (int c = 0; c < 4; c++) {
                int gl = wn * 64 + ni * 8 + qid * 2 + (c & 1);
                float qv = qv_s[gl];
                float va = va_s[gl];
                #pragma unroll
                for (int mi = 0; mi < 2; mi++) {
                    float t = tanh_fast(qv + acc[mi][ni][c]);
                    part[mi * 2 + (c >> 1)] += va * t;
                }
            }
        }
    }

    // Reduce over the 4 lanes (qid) sharing each row.
    #pragma unroll
    for (int i = 0; i < 4; i++) {
        part[i] += __shfl_xor_sync(0xffffffffu, part[i], 1);
        part[i] += __shfl_xor_sync(0xffffffffu, part[i], 2);
    }
    if (qid == 0) {
        #pragma unroll
        for (int mi = 0; mi < 2; mi++)
            #pragma unroll
            for (int h = 0; h < 2; h++)
                atomicAdd(&sc_s[wm * 32 + mi * 16 + h * 8 + grp], part[mi * 2 + h]);
    }
    __syncthreads();
    if (tid < TM)
        g_scores[b * S_ + s0 + tid] = sc_s[tid] + Va_b[0];
}

// ---------------------------------------------------------------------------
// K3: softmax over S per batch row. grid=32, block=256 (8 elems/thread).
// ---------------------------------------------------------------------------
__global__ void k3_softmax(float* __restrict__ out_w) {
    int b = blockIdx.x;
    int tid = threadIdx.x;
    const float* sc = g_scores + b * S_;
    __shared__ float red_max[8];
    __shared__ float red_sum[8];

    float v[8];
    float lmax = -CUDART_INF_F;
    #pragma unroll
    for (int i = 0; i < 8; i++) {
        v[i] = sc[tid + i * 256];
        lmax = fmaxf(lmax, v[i]);
    }
    #pragma unroll
    for (int o = 16; o; o >>= 1)
        lmax = fmaxf(lmax, __shfl_xor_sync(0xffffffffu, lmax, o));
    if ((tid & 31) == 0) red_max[tid >> 5] = lmax;
    __syncthreads();
    float m = red_max[0];
    #pragma unroll
    for (int w = 1; w < 8; w++) m = fmaxf(m, red_max[w]);

    float lsum = 0.f;
    #pragma unroll
    for (int i = 0; i < 8; i++) {
        v[i] = __expf(v[i] - m);
        lsum += v[i];
    }
    #pragma unroll
    for (int o = 16; o; o >>= 1)
        lsum += __shfl_xor_sync(0xffffffffu, lsum, o);
    if ((tid & 31) == 0) red_sum[tid >> 5] = lsum;
    __syncthreads();
    float s = 0.f;
    #pragma unroll
    for (int w = 0; w < 8; w++) s += red_sum[w];
    float inv = 1.f / s;
    #pragma unroll
    for (int i = 0; i < 8; i++)
        out_w[b * S_ + tid + i * 256] = v[i] * inv;
}

// ---------------------------------------------------------------------------
// K4: split-S context partials from fp16 keys (halves DRAM traffic).
// grid = 32*16 (b, s-chunk of 128), block=128: thread t owns cols 8t..8t+7.
// ---------------------------------------------------------------------------
__global__ void k4_context(const float* __restrict__ w) {
    int bx = blockIdx.x;
    int b  = bx >> 4;
    int sc = bx & 15;
    int tid = threadIdx.x;

    __shared__ float w_s[128];
    w_s[tid] = w[b * S_ + sc * 128 + tid];
    __syncthreads();

    const uint4* kb = (const uint4*)(g_keys_h + ((size_t)b * S_ + sc * 128) * H_) + tid;
    float acc[8] = {0.f, 0.f, 0.f, 0.f, 0.f, 0.f, 0.f, 0.f};
    #pragma unroll 4
    for (int s = 0; s < 128; s++) {
        uint4 k8 = kb[(size_t)s * (H_ / 8)];
        float ws = w_s[s];
        float2 p0 = __half22float2(*(__half2*)&k8.x);
        float2 p1 = __half22float2(*(__half2*)&k8.y);
        float2 p2 = __half22float2(*(__half2*)&k8.z);
        float2 p3 = __half22float2(*(__half2*)&k8.w);
        acc[0] += ws * p0.x; acc[1] += ws * p0.y;
        acc[2] += ws * p1.x; acc[3] += ws * p1.y;
        acc[4] += ws * p2.x; acc[5] += ws * p2.y;
        acc[6] += ws * p3.x; acc[7] += ws * p3.y;
    }
    float* dst = g_ctxp + (size_t)sc * (B_ * H_) + b * H_ + tid * 8;
    *(float4*)dst       = make_float4(acc[0], acc[1], acc[2], acc[3]);
    *(float4*)(dst + 4) = make_float4(acc[4], acc[5], acc[6], acc[7]);
}

__global__ void k5_reduce(float* __restrict__ ctx) {
    int idx = blockIdx.x * 256 + threadIdx.x;
    float a = 0.f;
    #pragma unroll
    for (int p = 0; p < 16; p++)
        a += g_ctxp[p * (B_ * H_) + idx];
    ctx[idx] = a;
}

// ---------------------------------------------------------------------------
// Launch: d_out[0..32767] = context [32,1,1024]; d_out[32768..98303] = weights.
// ---------------------------------------------------------------------------
extern "C" void kernel_launch(void* const* d_in, const int* in_sizes, int n_in,
                              void* d_out, int out_size) {
    const float* query = (const float*)d_in[0];
    const float* keys  = (const float*)d_in[1];
    const float* Wa_w  = (const float*)d_in[2];
    const float* Wa_b  = (const float*)d_in[3];
    const float* Ua_w  = (const float*)d_in[4];
    const float* Ua_b  = (const float*)d_in[5];
    const float* Va_w  = (const float*)d_in[6];
    const float* Va_b  = (const float*)d_in[7];

    float* ctx  = (float*)d_out;
    float* wout = ctx + B_ * H_;

    static int init_done = 0;
    static __half* keys_h_p = nullptr;
    static __half* Ua_h_p = nullptr;
    if (!init_done) {
        cudaFuncSetAttribute(k2_scores, cudaFuncAttributeMaxDynamicSharedMemorySize, SM_TOTAL);
        cudaGetSymbolAddress((void**)&keys_h_p, g_keys_h);
        cudaGetSymbolAddress((void**)&Ua_h_p, g_Ua_h);
        init_done = 1;
    }

    k0_cvt2<<<KEYS_BLKS + UA_BLKS, 256>>>(keys, keys_h_p, Ua_w, Ua_h_p);
    k1_qproj<<<dim3(32, 8), 256>>>(query, Wa_w, Wa_b, Ua_b);
    k2_scores<<<(B_ * S_) / TM, 128, SM_TOTAL>>>(Va_w, Va_b);
    k3_softmax<<<B_, 256>>>(wout);
    k4_context<<<B_ * 16, 128>>>(wout);
    k5_reduce<<<(B_ * H_) / 256, 256>>>(ctx);
}

// round 15
// speedup vs baseline: 1.0412x; 1.0412x over previous
#include <cuda_runtime.h>
#include <cuda_fp16.h>
#include <cstdint>
#include <math_constants.h>

#define B_ 32
#define S_ 2048
#define H_ 1024

// Scratch (no device allocation allowed)
__device__ float  g_qadd[B_ * H_];          // Wa_b + Ua_b + query @ Wa^T   [B,H]
__device__ float  g_scores[B_ * S_];        // pre-softmax scores           [B,S]
__device__ float  g_ctxp[16 * B_ * H_];     // K4 split-S partials
__device__ __half g_keys_h[B_ * S_ * H_];   // fp16 copy of keys (134 MB)
__device__ __half g_Ua_h[H_ * H_];          // fp16 copy of Ua   (2 MB)

__device__ __forceinline__ float tanh_fast(float x) {
    float y;
    asm("tanh.approx.f32 %0, %1;" : "=f"(y) : "f"(x));
    return y;
}

__device__ __forceinline__ uint32_t smem_u32(const void* p) {
    uint32_t a;
    asm("{ .reg .u64 t; cvta.to.shared.u64 t, %1; cvt.u32.u64 %0, t; }" : "=r"(a) : "l"(p));
    return a;
}

__device__ __forceinline__ void ldsm4(uint32_t& r0, uint32_t& r1, uint32_t& r2, uint32_t& r3,
                                      uint32_t addr) {
    asm volatile("ldmatrix.sync.aligned.m8n8.x4.shared.b16 {%0,%1,%2,%3}, [%4];"
                 : "=r"(r0), "=r"(r1), "=r"(r2), "=r"(r3) : "r"(addr));
}

// ---------------------------------------------------------------------------
// K0: fp32 -> fp16 conversion, keys + Ua in one launch (8 elems/thread).
// ---------------------------------------------------------------------------
#define KEYS_BLKS ((B_ * S_ * H_) / 2048)   // 32768
#define UA_BLKS   ((H_ * H_) / 2048)        // 512

__global__ void k0_cvt2(const float* __restrict__ keys, __half* __restrict__ keys_h,
                        const float* __restrict__ Ua,   __half* __restrict__ Ua_h) {
    int bx = blockIdx.x;
    const float* src;
    __half* dst;
    int base;
    if (bx < KEYS_BLKS) { src = keys; dst = keys_h; base = bx; }
    else                { src = Ua;   dst = Ua_h;   base = bx - KEYS_BLKS; }
    int i = (base * 256 + threadIdx.x) * 8;
    float4 f0 = *(const float4*)(src + i);
    float4 f1 = *(const float4*)(src + i + 4);
    __half2 h[4];
    h[0] = __floats2half2_rn(f0.x, f0.y);
    h[1] = __floats2half2_rn(f0.z, f0.w);
    h[2] = __floats2half2_rn(f1.x, f1.y);
    h[3] = __floats2half2_rn(f1.z, f1.w);
    *(uint4*)(dst + i) = *(uint4*)h;
}

// ---------------------------------------------------------------------------
// K1: qadd[b][g] = Wa_b[g] + Ua_b[g] + sum_h query[b][h] * Wa_w[g][h]
// ---------------------------------------------------------------------------
__global__ void k1_qproj(const float* __restrict__ query,
                         const float* __restrict__ Wa_w,
                         const float* __restrict__ Wa_b,
                         const float* __restrict__ Ua_b) {
    int b = blockIdx.x;
    int g0 = blockIdx.y * 128;
    __shared__ float q_s[H_];
    for (int i = threadIdx.x; i < H_; i += blockDim.x)
        q_s[i] = query[b * H_ + i];
    __syncthreads();

    int warp = threadIdx.x >> 5;
    int lane = threadIdx.x & 31;
    for (int gi = 0; gi < 16; gi++) {
        int g = g0 + warp * 16 + gi;
        const float* wrow = Wa_w + (size_t)g * H_;
        float acc = 0.f;
        #pragma unroll 8
        for (int h = lane; h < H_; h += 32)
            acc += q_s[h] * wrow[h];
        #pragma unroll
        for (int off = 16; off; off >>= 1)
            acc += __shfl_xor_sync(0xffffffffu, acc, off);
        if (lane == 0)
            g_qadd[b * H_ + g] = acc + Wa_b[g] + Ua_b[g];
    }
}

// ---------------------------------------------------------------------------
// K2: fused scores GEMM — exact R13 configuration (measured 377us, tensor 61%):
// mma.sync.m16n8k16.f16 + ldmatrix, single fragment set, 4 CTAs/SM.
// (R14 lesson: duplicate frag sets cost occ 4->3, regressed ~30us —
// cross-CTA concurrency beats intra-warp ILP at this occupancy.)
// CTA tile M=64 x N=128, 128 threads (4 warps, warp tile 32x64),
// TK=64 halves/chunk, 2-stage cp.async pipeline over global chunk counter.
// Row pitch 72 halves (144 B): LDSM phase addresses conflict-free.
// ---------------------------------------------------------------------------
#define TM 64
#define TN 128
#define TK 64                          // halves per k-chunk
#define NCHUNK (H_ / TK)               // 16 per nt
#define NT (H_ / TN)                   // 8 feature tiles
#define TOTC (NT * NCHUNK)             // 128 global chunks
#define SPADH 72                       // halves per row (144 B pitch)
#define A_TILE_B (TM * SPADH * 2)      // 9216 bytes
#define B_TILE_B (TN * SPADH * 2)      // 18432 bytes
// dynamic smem byte offsets
#define SM_SC  0                       // 64 floats
#define SM_QV  256                     // 128 floats
#define SM_VA  768                     // 128 floats
#define SM_A   1536                    // 2 buffers x 9216
#define SM_B   (SM_A + 2 * A_TILE_B)   // 2 buffers x 18432
#define SM_TOTAL (SM_B + 2 * B_TILE_B) // 56832

__device__ __forceinline__ void cp16(uint32_t dst, const void* src) {
    asm volatile("cp.async.cg.shared.global [%0], [%1], 16;" :: "r"(dst), "l"(src));
}

// 128 threads stage A tile (64 rows x 8 x 16B): 4 cp.async/thread.
__device__ __forceinline__ void stage_A(const __half* __restrict__ src,
                                        int kt, uint32_t buf) {
    int tid = threadIdx.x;
    #pragma unroll
    for (int i = 0; i < 4; i++) {
        int idx = i * 128 + tid;
        int row = idx >> 3, c = idx & 7;
        cp16(buf + (uint32_t)(row * (SPADH * 2) + c * 16),
             src + (size_t)row * H_ + kt * TK + c * 8);
    }
}

// 128 threads stage B tile (128 rows x 8 x 16B): 8 cp.async/thread.
__device__ __forceinline__ void stage_B(const __half* __restrict__ src,
                                        int kt, uint32_t buf) {
    int tid = threadIdx.x;
    #pragma unroll
    for (int i = 0; i < 8; i++) {
        int idx = i * 128 + tid;
        int row = idx >> 3, c = idx & 7;
        cp16(buf + (uint32_t)(row * (SPADH * 2) + c * 16),
             src + (size_t)row * H_ + kt * TK + c * 8);
    }
}

// Stage global chunk kc: keys k-chunk (kc & 15), Ua feature-block (kc >> 4).
__device__ __forceinline__ void stage_chunk(const __half* __restrict__ keys_blk,
                                            int kc, uint32_t sb) {
    int nb  = kc & 1;
    int knt = kc >> 4;
    int kkt = kc & 15;
    stage_A(keys_blk, kkt, sb + SM_A + nb * A_TILE_B);
    stage_B(g_Ua_h + (size_t)(knt * TN) * H_, kkt, sb + SM_B + nb * B_TILE_B);
    asm volatile("cp.async.commit_group;" ::: "memory");
}

__global__ __launch_bounds__(128, 4) void k2_scores(
    const float* __restrict__ Va_w,
    const float* __restrict__ Va_b) {

    extern __shared__ char smem[];
    uint32_t sb = smem_u32(smem);
    float* sc_s = (float*)(smem + SM_SC);
    float* qv_s = (float*)(smem + SM_QV);
    float* va_s = (float*)(smem + SM_VA);

    int tid  = threadIdx.x;
    int wid  = tid >> 5;
    int lane = tid & 31;
    int wm   = wid >> 1;          // 0..1 (32-row strips)
    int wn   = wid & 1;           // 0..1 (64-col strips)
    int grp  = lane >> 2;         // 0..7
    int qid  = lane & 3;          // 0..3

    // ldmatrix per-lane address components (halves)
    int a_row  = (lane & 7) + ((lane >> 3) & 1) * 8;
    int a_koff = ((lane >> 4) & 1) * 8;
    int b_n    = (lane & 7) + ((lane >> 4) & 1) * 8;
    int b_koff = ((lane >> 3) & 1) * 8;

    int blk = blockIdx.x;
    int b   = blk >> 5;                 // 32 s-tiles per batch
    int s0  = (blk & 31) * TM;
    const __half* keys_blk = g_keys_h + ((size_t)b * S_ + s0) * H_;

    if (tid < TM) sc_s[tid] = 0.f;

    float part[4] = {0.f, 0.f, 0.f, 0.f};

    for (int nt = 0; nt < NT; nt++) {
        __syncthreads();   // prev epilogue reads done before qv_s/va_s rewrite
        qv_s[tid] = g_qadd[b * H_ + nt * TN + tid];
        va_s[tid] = Va_w[nt * TN + tid];

        if (nt == 0)
            stage_chunk(keys_blk, 0, sb);   // prologue: stage global chunk 0

        float acc[2][8][4];
        #pragma unroll
        for (int mi = 0; mi < 2; mi++)
            #pragma unroll
            for (int ni = 0; ni < 8; ni++)
                #pragma unroll
                for (int c = 0; c < 4; c++)
                    acc[mi][ni][c] = 0.f;

        for (int kt = 0; kt < NCHUNK; kt++) {
            int kc  = nt * NCHUNK + kt;
            int cur = kc & 1;

            asm volatile("cp.async.wait_group 0;" ::: "memory");
            __syncthreads();   // chunk kc visible; reads of buf cur^1 done

            if (kc + 1 < TOTC)
                stage_chunk(keys_blk, kc + 1, sb);   // overlaps compute of kc

            uint32_t aba = sb + SM_A + cur * A_TILE_B;
            uint32_t bba = sb + SM_B + cur * B_TILE_B;
            uint32_t aaddr[2], baddr[4];
            #pragma unroll
            for (int mi = 0; mi < 2; mi++)
                aaddr[mi] = aba + (uint32_t)(((wm * 32 + mi * 16 + a_row) * SPADH + a_koff) * 2);
            #pragma unroll
            for (int p = 0; p < 4; p++)
                baddr[p] = bba + (uint32_t)(((wn * 64 + p * 16 + b_n) * SPADH + b_koff) * 2);

            #pragma unroll
            for (int k16 = 0; k16 < TK / 16; k16++) {
                uint32_t kb = k16 * 32;   // bytes: 16 halves
                uint32_t af[2][4];
                uint32_t bf[8][2];
                #pragma unroll
                for (int mi = 0; mi < 2; mi++)
                    ldsm4(af[mi][0], af[mi][1], af[mi][2], af[mi][3], aaddr[mi] + kb);
                #pragma unroll
                for (int p = 0; p < 4; p++)
                    ldsm4(bf[2*p][0], bf[2*p][1], bf[2*p+1][0], bf[2*p+1][1], baddr[p] + kb);
                #pragma unroll
                for (int mi = 0; mi < 2; mi++)
                    #pragma unroll
                    for (int ni = 0; ni < 8; ni++) {
                        asm volatile(
                            "mma.sync.aligned.m16n8k16.row.col.f32.f16.f16.f32 "
                            "{%0,%1,%2,%3}, {%4,%5,%6,%7}, {%8,%9}, {%0,%1,%2,%3};\n"
                            : "+f"(acc[mi][ni][0]), "+f"(acc[mi][ni][1]),
                              "+f"(acc[mi][ni][2]), "+f"(acc[mi][ni][3])
                            : "r"(af[mi][0]), "r"(af[mi][1]),
                              "r"(af[mi][2]), "r"(af[mi][3]),
                              "r"(bf[ni][0]), "r"(bf[ni][1]));
                    }
            }
        }

        // Epilogue: tanh + Va fold into per-row partials.
        #pragma unroll
        for (int ni = 0; ni < 8; ni++) {
            #pragma unroll
            for (int c = 0; c < 4; c++) {
                int gl = wn * 64 + ni * 8 + qid * 2 + (c & 1);
                float qv = qv_s[gl];
                float va = va_s[gl];
                #pragma unroll
                for (int mi = 0; mi < 2; mi++) {
                    float t = tanh_fast(qv + acc[mi][ni][c]);
                    part[mi * 2 + (c >> 1)] += va * t;
                }
            }
        }
    }

    // Reduce over the 4 lanes (qid) sharing each row.
    #pragma unroll
    for (int i = 0; i < 4; i++) {
        part[i] += __shfl_xor_sync(0xffffffffu, part[i], 1);
        part[i] += __shfl_xor_sync(0xffffffffu, part[i], 2);
    }
    if (qid == 0) {
        #pragma unroll
        for (int mi = 0; mi < 2; mi++)
            #pragma unroll
            for (int h = 0; h < 2; h++)
                atomicAdd(&sc_s[wm * 32 + mi * 16 + h * 8 + grp], part[mi * 2 + h]);
    }
    __syncthreads();
    if (tid < TM)
        g_scores[b * S_ + s0 + tid] = sc_s[tid] + Va_b[0];
}

// ---------------------------------------------------------------------------
// K3: softmax over S per batch row. grid=32, block=256 (8 elems/thread).
// ---------------------------------------------------------------------------
__global__ void k3_softmax(float* __restrict__ out_w) {
    int b = blockIdx.x;
    int tid = threadIdx.x;
    const float* sc = g_scores + b * S_;
    __shared__ float red_max[8];
    __shared__ float red_sum[8];

    float v[8];
    float lmax = -CUDART_INF_F;
    #pragma unroll
    for (int i = 0; i < 8; i++) {
        v[i] = sc[tid + i * 256];
        lmax = fmaxf(lmax, v[i]);
    }
    #pragma unroll
    for (int o = 16; o; o >>= 1)
        lmax = fmaxf(lmax, __shfl_xor_sync(0xffffffffu, lmax, o));
    if ((tid & 31) == 0) red_max[tid >> 5] = lmax;
    __syncthreads();
    float m = red_max[0];
    #pragma unroll
    for (int w = 1; w < 8; w++) m = fmaxf(m, red_max[w]);

    float lsum = 0.f;
    #pragma unroll
    for (int i = 0; i < 8; i++) {
        v[i] = __expf(v[i] - m);
        lsum += v[i];
    }
    #pragma unroll
    for (int o = 16; o; o >>= 1)
        lsum += __shfl_xor_sync(0xffffffffu, lsum, o);
    if ((tid & 31) == 0) red_sum[tid >> 5] = lsum;
    __syncthreads();
    float s = 0.f;
    #pragma unroll
    for (int w = 0; w < 8; w++) s += red_sum[w];
    float inv = 1.f / s;
    #pragma unroll
    for (int i = 0; i < 8; i++)
        out_w[b * S_ + tid + i * 256] = v[i] * inv;
}

// ---------------------------------------------------------------------------
// K4: split-S context partials from fp16 keys (halves DRAM traffic).
// grid = 32*16 (b, s-chunk of 128), block=128: thread t owns cols 8t..8t+7.
// ---------------------------------------------------------------------------
__global__ void k4_context(const float* __restrict__ w) {
    int bx = blockIdx.x;
    int b  = bx >> 4;
    int sc = bx & 15;
    int tid = threadIdx.x;

    __shared__ float w_s[128];
    w_s[tid] = w[b * S_ + sc * 128 + tid];
    __syncthreads();

    const uint4* kb = (const uint4*)(g_keys_h + ((size_t)b * S_ + sc * 128) * H_) + tid;
    float acc[8] = {0.f, 0.f, 0.f, 0.f, 0.f, 0.f, 0.f, 0.f};
    #pragma unroll 4
    for (int s = 0; s < 128; s++) {
        uint4 k8 = kb[(size_t)s * (H_ / 8)];
        float ws = w_s[s];
        float2 p0 = __half22float2(*(__half2*)&k8.x);
        float2 p1 = __half22float2(*(__half2*)&k8.y);
        float2 p2 = __half22float2(*(__half2*)&k8.z);
        float2 p3 = __half22float2(*(__half2*)&k8.w);
        acc[0] += ws * p0.x; acc[1] += ws * p0.y;
        acc[2] += ws * p1.x; acc[3] += ws * p1.y;
        acc[4] += ws * p2.x; acc[5] += ws * p2.y;
        acc[6] += ws * p3.x; acc[7] += ws * p3.y;
    }
    float* dst = g_ctxp + (size_t)sc * (B_ * H_) + b * H_ + tid * 8;
    *(float4*)dst       = make_float4(acc[0], acc[1], acc[2], acc[3]);
    *(float4*)(dst + 4) = make_float4(acc[4], acc[5], acc[6], acc[7]);
}

__global__ void k5_reduce(float* __restrict__ ctx) {
    int idx = blockIdx.x * 256 + threadIdx.x;
    float a = 0.f;
    #pragma unroll
    for (int p = 0; p < 16; p++)
        a += g_ctxp[p * (B_ * H_) + idx];
    ctx[idx] = a;
}

// ---------------------------------------------------------------------------
// Launch: d_out[0..32767] = context [32,1,1024]; d_out[32768..98303] = weights.
// ---------------------------------------------------------------------------
extern "C" void kernel_launch(void* const* d_in, const int* in_sizes, int n_in,
                              void* d_out, int out_size) {
    const float* query = (const float*)d_in[0];
    const float* keys  = (const float*)d_in[1];
    const float* Wa_w  = (const float*)d_in[2];
    const float* Wa_b  = (const float*)d_in[3];
    const float* Ua_w  = (const float*)d_in[4];
    const float* Ua_b  = (const float*)d_in[5];
    const float* Va_w  = (const float*)d_in[6];
    const float* Va_b  = (const float*)d_in[7];

    float* ctx  = (float*)d_out;
    float* wout = ctx + B_ * H_;

    static int init_done = 0;
    static __half* keys_h_p = nullptr;
    static __half* Ua_h_p = nullptr;
    if (!init_done) {
        cudaFuncSetAttribute(k2_scores, cudaFuncAttributeMaxDynamicSharedMemorySize, SM_TOTAL);
        cudaGetSymbolAddress((void**)&keys_h_p, g_keys_h);
        cudaGetSymbolAddress((void**)&Ua_h_p, g_Ua_h);
        init_done = 1;
    }

    k0_cvt2<<<KEYS_BLKS + UA_BLKS, 256>>>(keys, keys_h_p, Ua_w, Ua_h_p);
    k1_qproj<<<dim3(32, 8), 256>>>(query, Wa_w, Wa_b, Ua_b);
    k2_scores<<<(B_ * S_) / TM, 128, SM_TOTAL>>>(Va_w, Va_b);
    k3_softmax<<<B_, 256>>>(wout);
    k4_context<<<B_ * 16, 128>>>(wout);
    k5_reduce<<<(B_ * H_) / 256, 256>>>(ctx);
}

// round 16
// speedup vs baseline: 1.0885x; 1.0454x over previous
#include <cuda_runtime.h>
#include <cuda_fp16.h>
#include <cstdint>
#include <math_constants.h>

#define B_ 32
#define S_ 2048
#define H_ 1024

// Scratch (no device allocation allowed)
__device__ float  g_qadd[B_ * H_];          // Wa_b + Ua_b + query @ Wa^T   [B,H]
__device__ float  g_scores[B_ * S_];        // pre-softmax scores           [B,S]
__device__ float  g_ctxp[32 * B_ * H_];     // K4 split-S partials (32 chunks)
__device__ __half g_keys_h[B_ * S_ * H_];   // fp16 copy of keys (134 MB)
__device__ __half g_Ua_h[H_ * H_];          // fp16 copy of Ua   (2 MB)

__device__ __forceinline__ float tanh_fast(float x) {
    float y;
    asm("tanh.approx.f32 %0, %1;" : "=f"(y) : "f"(x));
    return y;
}

__device__ __forceinline__ uint32_t smem_u32(const void* p) {
    uint32_t a;
    asm("{ .reg .u64 t; cvta.to.shared.u64 t, %1; cvt.u32.u64 %0, t; }" : "=r"(a) : "l"(p));
    return a;
}

__device__ __forceinline__ void ldsm4(uint32_t& r0, uint32_t& r1, uint32_t& r2, uint32_t& r3,
                                      uint32_t addr) {
    asm volatile("ldmatrix.sync.aligned.m8n8.x4.shared.b16 {%0,%1,%2,%3}, [%4];"
                 : "=r"(r0), "=r"(r1), "=r"(r2), "=r"(r3) : "r"(addr));
}

// ---------------------------------------------------------------------------
// K0K1: heterogeneous launch.
//   blocks [0, KEYS_BLKS)                 : keys fp32 -> fp16 (8 elems/thread)
//   blocks [KEYS_BLKS, KEYS_BLKS+UA_BLKS) : Ua   fp32 -> fp16
//   blocks [KEYS_BLKS+UA_BLKS, +256)      : qproj — rides in the conversion's
//                                           bandwidth shadow instead of
//                                           serializing behind it.
// ---------------------------------------------------------------------------
#define KEYS_BLKS ((B_ * S_ * H_) / 2048)   // 32768
#define UA_BLKS   ((H_ * H_) / 2048)        // 512
#define QP_BLKS   256                       // 32 b x 8 g-blocks

__global__ void k0k1(const float* __restrict__ keys, __half* __restrict__ keys_h,
                     const float* __restrict__ Ua,   __half* __restrict__ Ua_h,
                     const float* __restrict__ query,
                     const float* __restrict__ Wa_w,
                     const float* __restrict__ Wa_b,
                     const float* __restrict__ Ua_b) {
    int bx = blockIdx.x;
    if (bx < KEYS_BLKS + UA_BLKS) {
        const float* src;
        __half* dst;
        int base;
        if (bx < KEYS_BLKS) { src = keys; dst = keys_h; base = bx; }
        else                { src = Ua;   dst = Ua_h;   base = bx - KEYS_BLKS; }
        int i = (base * 256 + threadIdx.x) * 8;
        float4 f0 = *(const float4*)(src + i);
        float4 f1 = *(const float4*)(src + i + 4);
        __half2 h[4];
        h[0] = __floats2half2_rn(f0.x, f0.y);
        h[1] = __floats2half2_rn(f0.z, f0.w);
        h[2] = __floats2half2_rn(f1.x, f1.y);
        h[3] = __floats2half2_rn(f1.z, f1.w);
        *(uint4*)(dst + i) = *(uint4*)h;
        return;
    }

    // qproj: qadd[b][g] = Wa_b[g] + Ua_b[g] + sum_h query[b][h] * Wa_w[g][h]
    int qb = bx - KEYS_BLKS - UA_BLKS;     // 0..255
    int b  = qb >> 3;
    int g0 = (qb & 7) * 128;
    __shared__ float q_s[H_];
    for (int i = threadIdx.x; i < H_; i += blockDim.x)
        q_s[i] = query[b * H_ + i];
    __syncthreads();

    int warp = threadIdx.x >> 5;
    int lane = threadIdx.x & 31;
    for (int gi = 0; gi < 16; gi++) {
        int g = g0 + warp * 16 + gi;
        const float* wrow = Wa_w + (size_t)g * H_;
        float acc = 0.f;
        #pragma unroll 8
        for (int h = lane; h < H_; h += 32)
            acc += q_s[h] * wrow[h];
        #pragma unroll
        for (int off = 16; off; off >>= 1)
            acc += __shfl_xor_sync(0xffffffffu, acc, off);
        if (lane == 0)
            g_qadd[b * H_ + g] = acc + Wa_b[g] + Ua_b[g];
    }
}

// ---------------------------------------------------------------------------
// K2: fused scores GEMM — FROZEN R13 configuration (measured 377us, tensor 61%):
// mma.sync.m16n8k16.f16 + ldmatrix, single fragment set, 4 CTAs/SM.
// CTA tile M=64 x N=128, 128 threads (4 warps, warp tile 32x64),
// TK=64 halves/chunk, 2-stage cp.async pipeline over global chunk counter.
// Row pitch 72 halves (144 B): LDSM phase addresses conflict-free.
// ---------------------------------------------------------------------------
#define TM 64
#define TN 128
#define TK 64                          // halves per k-chunk
#define NCHUNK (H_ / TK)               // 16 per nt
#define NT (H_ / TN)                   // 8 feature tiles
#define TOTC (NT * NCHUNK)             // 128 global chunks
#define SPADH 72                       // halves per row (144 B pitch)
#define A_TILE_B (TM * SPADH * 2)      // 9216 bytes
#define B_TILE_B (TN * SPADH * 2)      // 18432 bytes
// dynamic smem byte offsets
#define SM_SC  0                       // 64 floats
#define SM_QV  256                     // 128 floats
#define SM_VA  768                     // 128 floats
#define SM_A   1536                    // 2 buffers x 9216
#define SM_B   (SM_A + 2 * A_TILE_B)   // 2 buffers x 18432
#define SM_TOTAL (SM_B + 2 * B_TILE_B) // 56832

__device__ __forceinline__ void cp16(uint32_t dst, const void* src) {
    asm volatile("cp.async.cg.shared.global [%0], [%1], 16;" :: "r"(dst), "l"(src));
}

// 128 threads stage A tile (64 rows x 8 x 16B): 4 cp.async/thread.
__device__ __forceinline__ void stage_A(const __half* __restrict__ src,
                                        int kt, uint32_t buf) {
    int tid = threadIdx.x;
    #pragma unroll
    for (int i = 0; i < 4; i++) {
        int idx = i * 128 + tid;
        int row = idx >> 3, c = idx & 7;
        cp16(buf + (uint32_t)(row * (SPADH * 2) + c * 16),
             src + (size_t)row * H_ + kt * TK + c * 8);
    }
}

// 128 threads stage B tile (128 rows x 8 x 16B): 8 cp.async/thread.
__device__ __forceinline__ void stage_B(const __half* __restrict__ src,
                                        int kt, uint32_t buf) {
    int tid = threadIdx.x;
    #pragma unroll
    for (int i = 0; i < 8; i++) {
        int idx = i * 128 + tid;
        int row = idx >> 3, c = idx & 7;
        cp16(buf + (uint32_t)(row * (SPADH * 2) + c * 16),
             src + (size_t)row * H_ + kt * TK + c * 8);
    }
}

// Stage global chunk kc: keys k-chunk (kc & 15), Ua feature-block (kc >> 4).
__device__ __forceinline__ void stage_chunk(const __half* __restrict__ keys_blk,
                                            int kc, uint32_t sb) {
    int nb  = kc & 1;
    int knt = kc >> 4;
    int kkt = kc & 15;
    stage_A(keys_blk, kkt, sb + SM_A + nb * A_TILE_B);
    stage_B(g_Ua_h + (size_t)(knt * TN) * H_, kkt, sb + SM_B + nb * B_TILE_B);
    asm volatile("cp.async.commit_group;" ::: "memory");
}

__global__ __launch_bounds__(128, 4) void k2_scores(
    const float* __restrict__ Va_w,
    const float* __restrict__ Va_b) {

    extern __shared__ char smem[];
    uint32_t sb = smem_u32(smem);
    float* sc_s = (float*)(smem + SM_SC);
    float* qv_s = (float*)(smem + SM_QV);
    float* va_s = (float*)(smem + SM_VA);

    int tid  = threadIdx.x;
    int wid  = tid >> 5;
    int lane = tid & 31;
    int wm   = wid >> 1;          // 0..1 (32-row strips)
    int wn   = wid & 1;           // 0..1 (64-col strips)
    int grp  = lane >> 2;         // 0..7
    int qid  = lane & 3;          // 0..3

    // ldmatrix per-lane address components (halves)
    int a_row  = (lane & 7) + ((lane >> 3) & 1) * 8;
    int a_koff = ((lane >> 4) & 1) * 8;
    int b_n    = (lane & 7) + ((lane >> 4) & 1) * 8;
    int b_koff = ((lane >> 3) & 1) * 8;

    int blk = blockIdx.x;
    int b   = blk >> 5;                 // 32 s-tiles per batch
    int s0  = (blk & 31) * TM;
    const __half* keys_blk = g_keys_h + ((size_t)b * S_ + s0) * H_;

    if (tid < TM) sc_s[tid] = 0.f;

    float part[4] = {0.f, 0.f, 0.f, 0.f};

    for (int nt = 0; nt < NT; nt++) {
        __syncthreads();   // prev epilogue reads done before qv_s/va_s rewrite
        qv_s[tid] = g_qadd[b * H_ + nt * TN + tid];
        va_s[tid] = Va_w[nt * TN + tid];

        if (nt == 0)
            stage_chunk(keys_blk, 0, sb);   // prologue: stage global chunk 0

        float acc[2][8][4];
        #pragma unroll
        for (int mi = 0; mi < 2; mi++)
            #pragma unroll
            for (int ni = 0; ni < 8; ni++)
                #pragma unroll
                for (int c = 0; c < 4; c++)
                    acc[mi][ni][c] = 0.f;

        for (int kt = 0; kt < NCHUNK; kt++) {
            int kc  = nt * NCHUNK + kt;
            int cur = kc & 1;

            asm volatile("cp.async.wait_group 0;" ::: "memory");
            __syncthreads();   // chunk kc visible; reads of buf cur^1 done

            if (kc + 1 < TOTC)
                stage_chunk(keys_blk, kc + 1, sb);   // overlaps compute of kc

            uint32_t aba = sb + SM_A + cur * A_TILE_B;
            uint32_t bba = sb + SM_B + cur * B_TILE_B;
            uint32_t aaddr[2], baddr[4];
            #pragma unroll
            for (int mi = 0; mi < 2; mi++)
                aaddr[mi] = aba + (uint32_t)(((wm * 32 + mi * 16 + a_row) * SPADH + a_koff) * 2);
            #pragma unroll
            for (int p = 0; p < 4; p++)
                baddr[p] = bba + (uint32_t)(((wn * 64 + p * 16 + b_n) * SPADH + b_koff) * 2);

            #pragma unroll
            for (int k16 = 0; k16 < TK / 16; k16++) {
                uint32_t kb = k16 * 32;   // bytes: 16 halves
                uint32_t af[2][4];
                uint32_t bf[8][2];
                #pragma unroll
                for (int mi = 0; mi < 2; mi++)
                    ldsm4(af[mi][0], af[mi][1], af[mi][2], af[mi][3], aaddr[mi] + kb);
                #pragma unroll
                for (int p = 0; p < 4; p++)
                    ldsm4(bf[2*p][0], bf[2*p][1], bf[2*p+1][0], bf[2*p+1][1], baddr[p] + kb);
                #pragma unroll
                for (int mi = 0; mi < 2; mi++)
                    #pragma unroll
                    for (int ni = 0; ni < 8; ni++) {
                        asm volatile(
                            "mma.sync.aligned.m16n8k16.row.col.f32.f16.f16.f32 "
                            "{%0,%1,%2,%3}, {%4,%5,%6,%7}, {%8,%9}, {%0,%1,%2,%3};\n"
                            : "+f"(acc[mi][ni][0]), "+f"(acc[mi][ni][1]),
                              "+f"(acc[mi][ni][2]), "+f"(acc[mi][ni][3])
                            : "r"(af[mi][0]), "r"(af[mi][1]),
                              "r"(af[mi][2]), "r"(af[mi][3]),
                              "r"(bf[ni][0]), "r"(bf[ni][1]));
                    }
            }
        }

        // Epilogue: tanh + Va fold into per-row partials.
        #pragma unroll
        for (int ni = 0; ni < 8; ni++) {
            #pragma unroll
            for (int c = 0; c < 4; c++) {
                int gl = wn * 64 + ni * 8 + qid * 2 + (c & 1);
                float qv = qv_s[gl];
                float va = va_s[gl];
                #pragma unroll
                for (int mi = 0; mi < 2; mi++) {
                    float t = tanh_fast(qv + acc[mi][ni][c]);
                    part[mi * 2 + (c >> 1)] += va * t;
                }
            }
        }
    }

    // Reduce over the 4 lanes (qid) sharing each row.
    #pragma unroll
    for (int i = 0; i < 4; i++) {
        part[i] += __shfl_xor_sync(0xffffffffu, part[i], 1);
        part[i] += __shfl_xor_sync(0xffffffffu, part[i], 2);
    }
    if (qid == 0) {
        #pragma unroll
        for (int mi = 0; mi < 2; mi++)
            #pragma unroll
            for (int h = 0; h < 2; h++)
                atomicAdd(&sc_s[wm * 32 + mi * 16 + h * 8 + grp], part[mi * 2 + h]);
    }
    __syncthreads();
    if (tid < TM)
        g_scores[b * S_ + s0 + tid] = sc_s[tid] + Va_b[0];
}

// ---------------------------------------------------------------------------
// K3: softmax over S per batch row. grid=32, block=256 (8 elems/thread).
// ---------------------------------------------------------------------------
__global__ void k3_softmax(float* __restrict__ out_w) {
    int b = blockIdx.x;
    int tid = threadIdx.x;
    const float* sc = g_scores + b * S_;
    __shared__ float red_max[8];
    __shared__ float red_sum[8];

    float v[8];
    float lmax = -CUDART_INF_F;
    #pragma unroll
    for (int i = 0; i < 8; i++) {
        v[i] = sc[tid + i * 256];
        lmax = fmaxf(lmax, v[i]);
    }
    #pragma unroll
    for (int o = 16; o; o >>= 1)
        lmax = fmaxf(lmax, __shfl_xor_sync(0xffffffffu, lmax, o));
    if ((tid & 31) == 0) red_max[tid >> 5] = lmax;
    __syncthreads();
    float m = red_max[0];
    #pragma unroll
    for (int w = 1; w < 8; w++) m = fmaxf(m, red_max[w]);

    float lsum = 0.f;
    #pragma unroll
    for (int i = 0; i < 8; i++) {
        v[i] = __expf(v[i] - m);
        lsum += v[i];
    }
    #pragma unroll
    for (int o = 16; o; o >>= 1)
        lsum += __shfl_xor_sync(0xffffffffu, lsum, o);
    if ((tid & 31) == 0) red_sum[tid >> 5] = lsum;
    __syncthreads();
    float s = 0.f;
    #pragma unroll
    for (int w = 0; w < 8; w++) s += red_sum[w];
    float inv = 1.f / s;
    #pragma unroll
    for (int i = 0; i < 8; i++)
        out_w[b * S_ + tid + i * 256] = v[i] * inv;
}

// ---------------------------------------------------------------------------
// K4: split-S context partials from fp16 keys, 32 s-chunks of 64 rows
// (2x CTAs vs before: raises occupancy toward the 11us fp16-DRAM floor).
// grid = 32*32 (b, sc), block=128: thread t owns cols 8t..8t+7.
// ---------------------------------------------------------------------------
__global__ void k4_context(const float* __restrict__ w) {
    int bx = blockIdx.x;
    int b  = bx >> 5;
    int sc = bx & 31;
    int tid = threadIdx.x;

    __shared__ float w_s[64];
    if (tid < 64)
        w_s[tid] = w[b * S_ + sc * 64 + tid];
    __syncthreads();

    const uint4* kb = (const uint4*)(g_keys_h + ((size_t)b * S_ + sc * 64) * H_) + tid;
    float acc[8] = {0.f, 0.f, 0.f, 0.f, 0.f, 0.f, 0.f, 0.f};
    #pragma unroll 4
    for (int s = 0; s < 64; s++) {
        uint4 k8 = kb[(size_t)s * (H_ / 8)];
        float ws = w_s[s];
        float2 p0 = __half22float2(*(__half2*)&k8.x);
        float2 p1 = __half22float2(*(__half2*)&k8.y);
        float2 p2 = __half22float2(*(__half2*)&k8.z);
        float2 p3 = __half22float2(*(__half2*)&k8.w);
        acc[0] += ws * p0.x; acc[1] += ws * p0.y;
        acc[2] += ws * p1.x; acc[3] += ws * p1.y;
        acc[4] += ws * p2.x; acc[5] += ws * p2.y;
        acc[6] += ws * p3.x; acc[7] += ws * p3.y;
    }
    float* dst = g_ctxp + (size_t)sc * (B_ * H_) + b * H_ + tid * 8;
    *(float4*)dst       = make_float4(acc[0], acc[1], acc[2], acc[3]);
    *(float4*)(dst + 4) = make_float4(acc[4], acc[5], acc[6], acc[7]);
}

__global__ void k5_reduce(float* __restrict__ ctx) {
    int idx = blockIdx.x * 256 + threadIdx.x;
    float a = 0.f;
    #pragma unroll
    for (int p = 0; p < 32; p++)
        a += g_ctxp[p * (B_ * H_) + idx];
    ctx[idx] = a;
}

// ---------------------------------------------------------------------------
// Launch: d_out[0..32767] = context [32,1,1024]; d_out[32768..98303] = weights.
// ---------------------------------------------------------------------------
extern "C" void kernel_launch(void* const* d_in, const int* in_sizes, int n_in,
                              void* d_out, int out_size) {
    const float* query = (const float*)d_in[0];
    const float* keys  = (const float*)d_in[1];
    const float* Wa_w  = (const float*)d_in[2];
    const float* Wa_b  = (const float*)d_in[3];
    const float* Ua_w  = (const float*)d_in[4];
    const float* Ua_b  = (const float*)d_in[5];
    const float* Va_w  = (const float*)d_in[6];
    const float* Va_b  = (const float*)d_in[7];

    float* ctx  = (float*)d_out;
    float* wout = ctx + B_ * H_;

    static int init_done = 0;
    static __half* keys_h_p = nullptr;
    static __half* Ua_h_p = nullptr;
    if (!init_done) {
        cudaFuncSetAttribute(k2_scores, cudaFuncAttributeMaxDynamicSharedMemorySize, SM_TOTAL);
        cudaGetSymbolAddress((void**)&keys_h_p, g_keys_h);
        cudaGetSymbolAddress((void**)&Ua_h_p, g_Ua_h);
        init_done = 1;
    }

    k0k1<<<KEYS_BLKS + UA_BLKS + QP_BLKS, 256>>>(keys, keys_h_p, Ua_w, Ua_h_p,
                                                 query, Wa_w, Wa_b, Ua_b);
    k2_scores<<<(B_ * S_) / TM, 128, SM_TOTAL>>>(Va_w, Va_b);
    k3_softmax<<<B_, 256>>>(wout);
    k4_context<<<B_ * 32, 128>>>(wout);
    k5_reduce<<<(B_ * H_) / 256, 256>>>(ctx);
}

// round 17
// speedup vs baseline: 1.1242x; 1.0328x over previous
#include <cuda_runtime.h>
#include <cuda_fp16.h>
#include <cstdint>
#include <math_constants.h>

#define B_ 32
#define S_ 2048
#define H_ 1024

// Scratch (no device allocation allowed)
__device__ float  g_qadd[B_ * H_];          // Wa_b + Ua_b + query @ Wa^T   [B,H]
__device__ float  g_scores[B_ * S_];        // pre-softmax scores           [B,S]
__device__ float  g_ctxp[32 * B_ * H_];     // K4 split-S partials (32 chunks)
__device__ __half g_keys_h[B_ * S_ * H_];   // fp16 keys, written by K2 nt=0
__device__ __half g_Ua_h[H_ * H_];          // fp16 copy of Ua   (2 MB)

__device__ __forceinline__ float tanh_fast(float x) {
    float y;
    asm("tanh.approx.f32 %0, %1;" : "=f"(y) : "f"(x));
    return y;
}

__device__ __forceinline__ uint32_t smem_u32(const void* p) {
    uint32_t a;
    asm("{ .reg .u64 t; cvta.to.shared.u64 t, %1; cvt.u32.u64 %0, t; }" : "=r"(a) : "l"(p));
    return a;
}

__device__ __forceinline__ void ldsm4(uint32_t& r0, uint32_t& r1, uint32_t& r2, uint32_t& r3,
                                      uint32_t addr) {
    asm volatile("ldmatrix.sync.aligned.m8n8.x4.shared.b16 {%0,%1,%2,%3}, [%4];"
                 : "=r"(r0), "=r"(r1), "=r"(r2), "=r"(r3) : "r"(addr));
}

// ---------------------------------------------------------------------------
// K0K1: now tiny — Ua fp32->fp16 (512 blocks) + qproj (256 blocks).
// Keys conversion moved INTO K2 (each keys row belongs to exactly one K2 CTA).
// ---------------------------------------------------------------------------
#define UA_BLKS   ((H_ * H_) / 2048)        // 512
#define QP_BLKS   256                       // 32 b x 8 g-blocks

__global__ void k0k1(const float* __restrict__ Ua, __half* __restrict__ Ua_h,
                     const float* __restrict__ query,
                     const float* __restrict__ Wa_w,
                     const float* __restrict__ Wa_b,
                     const float* __restrict__ Ua_b) {
    int bx = blockIdx.x;
    if (bx < UA_BLKS) {
        int i = (bx * 256 + threadIdx.x) * 8;
        float4 f0 = *(const float4*)(Ua + i);
        float4 f1 = *(const float4*)(Ua + i + 4);
        __half2 h[4];
        h[0] = __floats2half2_rn(f0.x, f0.y);
        h[1] = __floats2half2_rn(f0.z, f0.w);
        h[2] = __floats2half2_rn(f1.x, f1.y);
        h[3] = __floats2half2_rn(f1.z, f1.w);
        *(uint4*)(Ua_h + i) = *(uint4*)h;
        return;
    }

    // qproj: qadd[b][g] = Wa_b[g] + Ua_b[g] + sum_h query[b][h] * Wa_w[g][h]
    int qb = bx - UA_BLKS;                 // 0..255
    int b  = qb >> 3;
    int g0 = (qb & 7) * 128;
    __shared__ float q_s[H_];
    for (int i = threadIdx.x; i < H_; i += blockDim.x)
        q_s[i] = query[b * H_ + i];
    __syncthreads();

    int warp = threadIdx.x >> 5;
    int lane = threadIdx.x & 31;
    for (int gi = 0; gi < 16; gi++) {
        int g = g0 + warp * 16 + gi;
        const float* wrow = Wa_w + (size_t)g * H_;
        float acc = 0.f;
        #pragma unroll 8
        for (int h = lane; h < H_; h += 32)
            acc += q_s[h] * wrow[h];
        #pragma unroll
        for (int off = 16; off; off >>= 1)
            acc += __shfl_xor_sync(0xffffffffu, acc, off);
        if (lane == 0)
            g_qadd[b * H_ + g] = acc + Wa_b[g] + Ua_b[g];
    }
}

// ---------------------------------------------------------------------------
// K2: fused scores GEMM — R13 core (frozen: m16n8k16 + ldmatrix, 4 CTAs/SM,
// TM=64 x TN=128, TK=64, 2-stage cp.async) PLUS in-kernel keys conversion:
// nt=0 A-staging reads fp32 keys (LDG -> cvt -> STS swizzled -> STG writeback
// to g_keys_h); nt=1..7 cp.async from g_keys_h as before. __syncthreads gives
// block-scope global visibility; cp.async.cg reads L2 (coherence point).
// Removes the 67us serial keys-conversion kernel.
// ---------------------------------------------------------------------------
#define TM 64
#define TN 128
#define TK 64                          // halves per k-chunk
#define NCHUNK (H_ / TK)               // 16 per nt
#define NT (H_ / TN)                   // 8 feature tiles
#define TOTC (NT * NCHUNK)             // 128 global chunks
#define SPADH 72                       // halves per row (144 B pitch)
#define A_TILE_B (TM * SPADH * 2)      // 9216 bytes
#define B_TILE_B (TN * SPADH * 2)      // 18432 bytes
// dynamic smem byte offsets
#define SM_SC  0                       // 64 floats
#define SM_QV  256                     // 128 floats
#define SM_VA  768                     // 128 floats
#define SM_A   1536                    // 2 buffers x 9216
#define SM_B   (SM_A + 2 * A_TILE_B)   // 2 buffers x 18432
#define SM_TOTAL (SM_B + 2 * B_TILE_B) // 56832

__device__ __forceinline__ void cp16(uint32_t dst, const void* src) {
    asm volatile("cp.async.cg.shared.global [%0], [%1], 16;" :: "r"(dst), "l"(src));
}

__device__ __forceinline__ void sts16(uint32_t addr, uint4 v) {
    asm volatile("st.shared.v4.b32 [%0], {%1,%2,%3,%4};"
                 :: "r"(addr), "r"(v.x), "r"(v.y), "r"(v.z), "r"(v.w) : "memory");
}

// nt=0 A-staging: fp32 keys -> fp16 smem (+ writeback to g_keys_h).
__device__ __forceinline__ void stage_A_cvt(const float* __restrict__ src32,
                                            __half* __restrict__ dst_h,
                                            int kt, uint32_t buf) {
    int tid = threadIdx.x;
    #pragma unroll
    for (int i = 0; i < 4; i++) {
        int idx = i * 128 + tid;
        int row = idx >> 3, c = idx & 7;
        const float* s = src32 + (size_t)row * H_ + kt * TK + c * 8;
        float4 f0 = *(const float4*)s;
        float4 f1 = *(const float4*)(s + 4);
        __half2 h[4];
        h[0] = __floats2half2_rn(f0.x, f0.y);
        h[1] = __floats2half2_rn(f0.z, f0.w);
        h[2] = __floats2half2_rn(f1.x, f1.y);
        h[3] = __floats2half2_rn(f1.z, f1.w);
        uint4 hv = *(uint4*)h;
        sts16(buf + (uint32_t)(row * (SPADH * 2) + c * 16), hv);
        *(uint4*)(dst_h + (size_t)row * H_ + kt * TK + c * 8) = hv;
    }
}

// fp16 A-staging via cp.async (nt >= 1).
__device__ __forceinline__ void stage_A(const __half* __restrict__ src,
                                        int kt, uint32_t buf) {
    int tid = threadIdx.x;
    #pragma unroll
    for (int i = 0; i < 4; i++) {
        int idx = i * 128 + tid;
        int row = idx >> 3, c = idx & 7;
        cp16(buf + (uint32_t)(row * (SPADH * 2) + c * 16),
             src + (size_t)row * H_ + kt * TK + c * 8);
    }
}

// 128 threads stage B tile (128 rows x 8 x 16B): 8 cp.async/thread.
__device__ __forceinline__ void stage_B(const __half* __restrict__ src,
                                        int kt, uint32_t buf) {
    int tid = threadIdx.x;
    #pragma unroll
    for (int i = 0; i < 8; i++) {
        int idx = i * 128 + tid;
        int row = idx >> 3, c = idx & 7;
        cp16(buf + (uint32_t)(row * (SPADH * 2) + c * 16),
             src + (size_t)row * H_ + kt * TK + c * 8);
    }
}

// Stage global chunk kc: keys k-chunk (kc & 15), Ua feature-block (kc >> 4).
// kc < 16 (nt=0): convert fp32 keys in-flight; else cp.async from g_keys_h.
__device__ __forceinline__ void stage_chunk(const float* __restrict__ keys32_blk,
                                            __half* __restrict__ keysh_blk,
                                            int kc, uint32_t sb) {
    int nb  = kc & 1;
    int knt = kc >> 4;
    int kkt = kc & 15;
    if (kc < NCHUNK)
        stage_A_cvt(keys32_blk, keysh_blk, kkt, sb + SM_A + nb * A_TILE_B);
    else
        stage_A(keysh_blk, kkt, sb + SM_A + nb * A_TILE_B);
    stage_B(g_Ua_h + (size_t)(knt * TN) * H_, kkt, sb + SM_B + nb * B_TILE_B);
    asm volatile("cp.async.commit_group;" ::: "memory");
}

__global__ __launch_bounds__(128, 4) void k2_scores(
    const float* __restrict__ keys,
    const float* __restrict__ Va_w,
    const float* __restrict__ Va_b) {

    extern __shared__ char smem[];
    uint32_t sb = smem_u32(smem);
    float* sc_s = (float*)(smem + SM_SC);
    float* qv_s = (float*)(smem + SM_QV);
    float* va_s = (float*)(smem + SM_VA);

    int tid  = threadIdx.x;
    int wid  = tid >> 5;
    int lane = tid & 31;
    int wm   = wid >> 1;          // 0..1 (32-row strips)
    int wn   = wid & 1;           // 0..1 (64-col strips)
    int grp  = lane >> 2;         // 0..7
    int qid  = lane & 3;          // 0..3

    // ldmatrix per-lane address components (halves)
    int a_row  = (lane & 7) + ((lane >> 3) & 1) * 8;
    int a_koff = ((lane >> 4) & 1) * 8;
    int b_n    = (lane & 7) + ((lane >> 4) & 1) * 8;
    int b_koff = ((lane >> 3) & 1) * 8;

    int blk = blockIdx.x;
    int b   = blk >> 5;                 // 32 s-tiles per batch
    int s0  = (blk & 31) * TM;
    const float* keys32_blk = keys + ((size_t)b * S_ + s0) * H_;
    __half*      keysh_blk  = g_keys_h + ((size_t)b * S_ + s0) * H_;

    if (tid < TM) sc_s[tid] = 0.f;

    float part[4] = {0.f, 0.f, 0.f, 0.f};

    for (int nt = 0; nt < NT; nt++) {
        __syncthreads();   // prev epilogue reads done before qv_s/va_s rewrite
        qv_s[tid] = g_qadd[b * H_ + nt * TN + tid];
        va_s[tid] = Va_w[nt * TN + tid];

        if (nt == 0)
            stage_chunk(keys32_blk, keysh_blk, 0, sb);   // prologue (cvt path)

        float acc[2][8][4];
        #pragma unroll
        for (int mi = 0; mi < 2; mi++)
            #pragma unroll
            for (int ni = 0; ni < 8; ni++)
                #pragma unroll
                for (int c = 0; c < 4; c++)
                    acc[mi][ni][c] = 0.f;

        for (int kt = 0; kt < NCHUNK; kt++) {
            int kc  = nt * NCHUNK + kt;
            int cur = kc & 1;

            asm volatile("cp.async.wait_group 0;" ::: "memory");
            __syncthreads();   // chunk kc visible (cp.async + STS); buf cur^1 free

            if (kc + 1 < TOTC)
                stage_chunk(keys32_blk, keysh_blk, kc + 1, sb);

            uint32_t aba = sb + SM_A + cur * A_TILE_B;
            uint32_t bba = sb + SM_B + cur * B_TILE_B;
            uint32_t aaddr[2], baddr[4];
            #pragma unroll
            for (int mi = 0; mi < 2; mi++)
                aaddr[mi] = aba + (uint32_t)(((wm * 32 + mi * 16 + a_row) * SPADH + a_koff) * 2);
            #pragma unroll
            for (int p = 0; p < 4; p++)
                baddr[p] = bba + (uint32_t)(((wn * 64 + p * 16 + b_n) * SPADH + b_koff) * 2);

            #pragma unroll
            for (int k16 = 0; k16 < TK / 16; k16++) {
                uint32_t kb = k16 * 32;   // bytes: 16 halves
                uint32_t af[2][4];
                uint32_t bf[8][2];
                #pragma unroll
                for (int mi = 0; mi < 2; mi++)
                    ldsm4(af[mi][0], af[mi][1], af[mi][2], af[mi][3], aaddr[mi] + kb);
                #pragma unroll
                for (int p = 0; p < 4; p++)
                    ldsm4(bf[2*p][0], bf[2*p][1], bf[2*p+1][0], bf[2*p+1][1], baddr[p] + kb);
                #pragma unroll
                for (int mi = 0; mi < 2; mi++)
                    #pragma unroll
                    for (int ni = 0; ni < 8; ni++) {
                        asm volatile(
                            "mma.sync.aligned.m16n8k16.row.col.f32.f16.f16.f32 "
                            "{%0,%1,%2,%3}, {%4,%5,%6,%7}, {%8,%9}, {%0,%1,%2,%3};\n"
                            : "+f"(acc[mi][ni][0]), "+f"(acc[mi][ni][1]),
                              "+f"(acc[mi][ni][2]), "+f"(acc[mi][ni][3])
                            : "r"(af[mi][0]), "r"(af[mi][1]),
                              "r"(af[mi][2]), "r"(af[mi][3]),
                              "r"(bf[ni][0]), "r"(bf[ni][1]));
                    }
            }
        }

        // Epilogue: tanh + Va fold into per-row partials.
        #pragma unroll
        for (int ni = 0; ni < 8; ni++) {
            #pragma unroll
            for (int c = 0; c < 4; c++) {
                int gl = wn * 64 + ni * 8 + qid * 2 + (c & 1);
                float qv = qv_s[gl];
                float va = va_s[gl];
                #pragma unroll
                for (int mi = 0; mi < 2; mi++) {
                    float t = tanh_fast(qv + acc[mi][ni][c]);
                    part[mi * 2 + (c >> 1)] += va * t;
                }
            }
        }
    }

    // Reduce over the 4 lanes (qid) sharing each row.
    #pragma unroll
    for (int i = 0; i < 4; i++) {
        part[i] += __shfl_xor_sync(0xffffffffu, part[i], 1);
        part[i] += __shfl_xor_sync(0xffffffffu, part[i], 2);
    }
    if (qid == 0) {
        #pragma unroll
        for (int mi = 0; mi < 2; mi++)
            #pragma unroll
            for (int h = 0; h < 2; h++)
                atomicAdd(&sc_s[wm * 32 + mi * 16 + h * 8 + grp], part[mi * 2 + h]);
    }
    __syncthreads();
    if (tid < TM)
        g_scores[b * S_ + s0 + tid] = sc_s[tid] + Va_b[0];
}

// ---------------------------------------------------------------------------
// K3: softmax over S per batch row. grid=32, block=256 (8 elems/thread).
// ---------------------------------------------------------------------------
__global__ void k3_softmax(float* __restrict__ out_w) {
    int b = blockIdx.x;
    int tid = threadIdx.x;
    const float* sc = g_scores + b * S_;
    __shared__ float red_max[8];
    __shared__ float red_sum[8];

    float v[8];
    float lmax = -CUDART_INF_F;
    #pragma unroll
    for (int i = 0; i < 8; i++) {
        v[i] = sc[tid + i * 256];
        lmax = fmaxf(lmax, v[i]);
    }
    #pragma unroll
    for (int o = 16; o; o >>= 1)
        lmax = fmaxf(lmax, __shfl_xor_sync(0xffffffffu, lmax, o));
    if ((tid & 31) == 0) red_max[tid >> 5] = lmax;
    __syncthreads();
    float m = red_max[0];
    #pragma unroll
    for (int w = 1; w < 8; w++) m = fmaxf(m, red_max[w]);

    float lsum = 0.f;
    #pragma unroll
    for (int i = 0; i < 8; i++) {
        v[i] = __expf(v[i] - m);
        lsum += v[i];
    }
    #pragma unroll
    for (int o = 16; o; o >>= 1)
        lsum += __shfl_xor_sync(0xffffffffu, lsum, o);
    if ((tid & 31) == 0) red_sum[tid >> 5] = lsum;
    __syncthreads();
    float s = 0.f;
    #pragma unroll
    for (int w = 0; w < 8; w++) s += red_sum[w];
    float inv = 1.f / s;
    #pragma unroll
    for (int i = 0; i < 8; i++)
        out_w[b * S_ + tid + i * 256] = v[i] * inv;
}

// ---------------------------------------------------------------------------
// K4: split-S context partials from fp16 keys, 32 s-chunks of 64 rows.
// grid = 32*32 (b, sc), block=128: thread t owns cols 8t..8t+7.
// ---------------------------------------------------------------------------
__global__ void k4_context(const float* __restrict__ w) {
    int bx = blockIdx.x;
    int b  = bx >> 5;
    int sc = bx & 31;
    int tid = threadIdx.x;

    __shared__ float w_s[64];
    if (tid < 64)
        w_s[tid] = w[b * S_ + sc * 64 + tid];
    __syncthreads();

    const uint4* kb = (const uint4*)(g_keys_h + ((size_t)b * S_ + sc * 64) * H_) + tid;
    float acc[8] = {0.f, 0.f, 0.f, 0.f, 0.f, 0.f, 0.f, 0.f};
    #pragma unroll 4
    for (int s = 0; s < 64; s++) {
        uint4 k8 = kb[(size_t)s * (H_ / 8)];
        float ws = w_s[s];
        float2 p0 = __half22float2(*(__half2*)&k8.x);
        float2 p1 = __half22float2(*(__half2*)&k8.y);
        float2 p2 = __half22float2(*(__half2*)&k8.z);
        float2 p3 = __half22float2(*(__half2*)&k8.w);
        acc[0] += ws * p0.x; acc[1] += ws * p0.y;
        acc[2] += ws * p1.x; acc[3] += ws * p1.y;
        acc[4] += ws * p2.x; acc[5] += ws * p2.y;
        acc[6] += ws * p3.x; acc[7] += ws * p3.y;
    }
    float* dst = g_ctxp + (size_t)sc * (B_ * H_) + b * H_ + tid * 8;
    *(float4*)dst       = make_float4(acc[0], acc[1], acc[2], acc[3]);
    *(float4*)(dst + 4) = make_float4(acc[4], acc[5], acc[6], acc[7]);
}

__global__ void k5_reduce(float* __restrict__ ctx) {
    int idx = blockIdx.x * 256 + threadIdx.x;
    float a = 0.f;
    #pragma unroll
    for (int p = 0; p < 32; p++)
        a += g_ctxp[p * (B_ * H_) + idx];
    ctx[idx] = a;
}

// ---------------------------------------------------------------------------
// Launch: d_out[0..32767] = context [32,1,1024]; d_out[32768..98303] = weights.
// ---------------------------------------------------------------------------
extern "C" void kernel_launch(void* const* d_in, const int* in_sizes, int n_in,
                              void* d_out, int out_size) {
    const float* query = (const float*)d_in[0];
    const float* keys  = (const float*)d_in[1];
    const float* Wa_w  = (const float*)d_in[2];
    const float* Wa_b  = (const float*)d_in[3];
    const float* Ua_w  = (const float*)d_in[4];
    const float* Ua_b  = (const float*)d_in[5];
    const float* Va_w  = (const float*)d_in[6];
    const float* Va_b  = (const float*)d_in[7];

    float* ctx  = (float*)d_out;
    float* wout = ctx + B_ * H_;

    static int init_done = 0;
    static __half* Ua_h_p = nullptr;
    if (!init_done) {
        cudaFuncSetAttribute(k2_scores, cudaFuncAttributeMaxDynamicSharedMemorySize, SM_TOTAL);
        cudaGetSymbolAddress((void**)&Ua_h_p, g_Ua_h);
        init_done = 1;
    }

    k0k1<<<UA_BLKS + QP_BLKS, 256>>>(Ua_w, Ua_h_p, query, Wa_w, Wa_b, Ua_b);
    k2_scores<<<(B_ * S_) / TM, 128, SM_TOTAL>>>(keys, Va_w, Va_b);
    k3_softmax<<<B_, 256>>>(wout);
    k4_context<<<B_ * 32, 128>>>(wout);
    k5_reduce<<<(B_ * H_) / 256, 256>>>(ctx);
}